// round 17
// baseline (speedup 1.0000x reference)
#include <cuda_runtime.h>
#include <math.h>

#define H 1024
#define W 1024
#define BATCH 16
#define CH 3
#define NPLANE (H * W)
#define NPIX (BATCH * NPLANE)

#define G0 0.13533528323661270f  /* exp(-2)   */
#define G1 0.60653065971263342f  /* exp(-0.5) */
#define T1C 0.41421356237f       /* tan(22.5 deg) */
#define T2C 2.41421356237f       /* tan(67.5 deg) */
#define BANDEPS 1e-3f
#define WEDGE   1e-4f            /* near-pi wedge (ref wraps past 180) */

#define TX 128      /* tile width (outputs)  */
#define TY 64       /* tile height (outputs) */
#define NT 128      /* threads per block     */
#define LW 136      /* img row width: cols x0-4 .. x0+131   */
#define BW 132      /* blurred row:   cols x0-2 .. x0+129   */

template<bool INTERIOR>
__device__ __forceinline__ void canny_body(
    const float* __restrict__ imgb,
    float* __restrict__ blb,
    float* __restrict__ out,
    int b, int x0, int y0, int t,
    float bh, float bv, float shb, float svb, float d0b, float d1b,
    float (*s_img)[CH][LW], float (*s_bl)[CH][BW], float (*s_mag)[BW],
    float (*sh_hB)[CH][5], float (*sh_hs)[CH][3], float (*sh_hd)[CH][3])
{
    /* main-column register rings (thread t owns output col x0+t) */
    float h0[CH], h1[CH], h2[CH], h3[CH], h4[CH];
    float hs0[CH], hs1[CH], hs2[CH];
    float hd0[CH], hd1[CH], hd2[CH];
    #pragma unroll
    for (int c = 0; c < CH; c++) {
        h0[c] = h1[c] = h2[c] = h3[c] = h4[c] = 0.0f;
        hs0[c] = hs1[c] = hs2[c] = 0.0f;
        hd0[c] = hd1[c] = hd2[c] = 0.0f;
    }
    float pm = 0.0f, pgx = 0.0f, pgy = 0.0f;

    const int lane = t & 31;
    const int wid  = t >> 5;
    const bool isHaloB = (lane == 31);             /* 4 threads, one per warp */
    const bool isHaloC = (lane == 31) && (wid < 2);
    const int  jB   = wid;
    const int  posB = (jB < 2) ? jB : jB + 128;    /* blur pos 0,1,130,131   */
    const int  posC = (jB == 0) ? 0 : 129;         /* mag pos 0 or 129       */

    /* zero halo rings (owner threads only; self-use, no barrier needed) */
    if (isHaloB) {
        #pragma unroll
        for (int c = 0; c < CH; c++)
            #pragma unroll
            for (int k = 0; k < 5; k++) sh_hB[jB][c][k] = 0.0f;
    }
    if (isHaloC) {
        #pragma unroll
        for (int c = 0; c < CH; c++)
            #pragma unroll
            for (int k = 0; k < 3; k++) { sh_hs[jB][c][k] = 0.0f; sh_hd[jB][c][k] = 0.0f; }
    }

    const int gxl = x0 - 4 + t;                            /* main img col  */
    const bool cAok = INTERIOR || ((unsigned)gxl < (unsigned)W);
    const bool isA2 = ((t & 15) == 15);                    /* 8 halo loaders */
    const int idx2 = 128 + (t >> 4);                       /* img idx 128..135 */
    const int gxl2 = x0 - 4 + idx2;
    const bool cA2ok = INTERIOR || ((unsigned)gxl2 < (unsigned)W);

    const size_t pbase = (size_t)b * NPLANE + (size_t)y0 * W + x0 + t;

    float* gm_out     = out + (size_t)3 * NPIX;
    float* orient_out = out + (size_t)4 * NPIX;
    float* thin_out   = out + (size_t)5 * NPIX;
    float* thresh_out = out + (size_t)6 * NPIX;
    float* early_out  = out + (size_t)7 * NPIX;

    auto loadA = [&](int y_img, float (*si)[LW]) {
        if (INTERIOR) {
            const size_t ro = (size_t)y_img * W;
            #pragma unroll
            for (int c = 0; c < CH; c++)
                si[c][t] = imgb[(size_t)c * NPLANE + ro + gxl];
            if (isA2) {
                #pragma unroll
                for (int c = 0; c < CH; c++)
                    si[c][idx2] = imgb[(size_t)c * NPLANE + ro + gxl2];
            }
        } else {
            const bool rAok = ((unsigned)y_img < (unsigned)H);
            const size_t ro = rAok ? (size_t)y_img * W : 0;
            const bool ok = rAok && cAok;
            #pragma unroll
            for (int c = 0; c < CH; c++)
                si[c][t] = ok ? imgb[(size_t)c * NPLANE + ro + gxl] : 0.0f;
            if (isA2) {
                const bool ok2 = rAok && cA2ok;
                #pragma unroll
                for (int c = 0; c < CH; c++)
                    si[c][idx2] = ok2 ? imgb[(size_t)c * NPLANE + ro + gxl2] : 0.0f;
            }
        }
    };

    auto phaseB = [&](int y_img, float (*si)[LW], float (*sb)[BW], int r5) {
        const int yb = y_img - 2;
        const bool rAok = INTERIOR || ((unsigned)y_img < (unsigned)H);
        const bool rBok = INTERIOR || ((unsigned)yb < (unsigned)H);
        const bool wr = (yb >= y0) && (yb < y0 + TY);
        float* wp = blb + ((size_t)yb * W + (x0 + t));
        /* main: blur col x0+t = sb pos t+2; img window si[t+2 .. t+6]
           (si index j  <->  img col x0-4+j; center t+4 <-> col x0+t) */
        #pragma unroll
        for (int c = 0; c < CH; c++) {
            const float v0 = si[c][t + 2], v1 = si[c][t + 3],
                        v2 = si[c][t + 4], v3 = si[c][t + 5],
                        v4 = si[c][t + 6];
            float hn = G0 * (v0 + v4) + G1 * (v1 + v3) + v2 + bh;
            if (!INTERIOR && !rAok) hn = 0.0f;
            h0[c] = h1[c]; h1[c] = h2[c]; h2[c] = h3[c]; h3[c] = h4[c]; h4[c] = hn;
            const float B = G0 * (h0[c] + h4[c]) + G1 * (h1[c] + h3[c]) + h2[c] + bv;
            sb[c][t + 2] = (INTERIOR || rBok) ? B : 0.0f;
            if (wr) __stcs(wp + (size_t)c * NPLANE, B);
        }
        /* halo: blur pos 0,1,130,131 (cols x0-2,x0-1,x0+128,x0+129) via smem rings */
        if (isHaloB) {
            const int i1 = (r5 + 1) % 5, i2 = (r5 + 2) % 5,
                      i3 = (r5 + 3) % 5, i4 = (r5 + 4) % 5;
            const int colH = x0 - 2 + posB;
            const bool cHok = INTERIOR || ((unsigned)colH < (unsigned)W);
            #pragma unroll
            for (int c = 0; c < CH; c++) {
                const float v0 = si[c][posB],     v1 = si[c][posB + 1],
                            v2 = si[c][posB + 2], v3 = si[c][posB + 3],
                            v4 = si[c][posB + 4];
                float hn = G0 * (v0 + v4) + G1 * (v1 + v3) + v2 + bh;
                if (!INTERIOR && !rAok) hn = 0.0f;
                float* rg = sh_hB[jB][c];
                rg[r5] = hn;
                const float B = G0 * (rg[i1] + hn) + G1 * (rg[i2] + rg[i4]) + rg[i3] + bv;
                sb[c][posB] = (INTERIOR || (rBok && cHok)) ? B : 0.0f;
            }
        }
    };

    auto phaseC = [&](int ym, float (*sb)[BW], float* mrow,
                      float& nm, float& ngx, float& ngy, int r3) {
        nm = 0.0f; ngx = 0.0f; ngy = 0.0f;
        const bool rMok = INTERIOR || ((unsigned)ym < (unsigned)H);
        /* main: mag col x0+t = mrow pos t+1; reads sb[t+1..t+3] (cols x0+t-1..x0+t+1) */
        #pragma unroll
        for (int c = 0; c < CH; c++) {
            const float b0 = sb[c][t + 1], b1 = sb[c][t + 2], b2 = sb[c][t + 3];
            const float hsn = b0 + 2.0f * b1 + b2;
            const float hdn = b0 - b2;
            hs0[c] = hs1[c]; hs1[c] = hs2[c]; hs2[c] = hsn;
            hd0[c] = hd1[c]; hd1[c] = hd2[c]; hd2[c] = hdn;
            const float gxv = (hd0[c] + 2.0f * hd1[c]) + hd2[c] + shb;
            const float gyv = hs0[c] - hs2[c] + svb;
            nm += sqrtf(gxv * gxv + gyv * gyv);
            ngx += gxv; ngy += gyv;
        }
        if (!rMok) nm = 0.0f;
        mrow[t + 1] = nm;
        /* halo: mag pos 0 / 129 (cols x0-1 / x0+128) via smem 3-rings */
        if (isHaloC) {
            const int i1 = (r3 + 1) % 3, i2 = (r3 + 2) % 3;
            float hm = 0.0f;
            #pragma unroll
            for (int c = 0; c < CH; c++) {
                const float b0 = sb[c][posC], b1 = sb[c][posC + 1], b2 = sb[c][posC + 2];
                const float hsn = b0 + 2.0f * b1 + b2;
                const float hdn = b0 - b2;
                float* rs = sh_hs[jB][c];
                float* rd = sh_hd[jB][c];
                const float gxv = (rd[i1] + 2.0f * rd[i2]) + hdn + shb;
                const float gyv = rs[i1] - hsn + svb;
                rs[r3] = hsn; rd[r3] = hdn;
                hm += sqrtf(gxv * gxv + gyv * gyv);
            }
            const bool cHok = (jB == 0) ? (INTERIOR || (x0 > 0))
                                        : (INTERIOR || (x0 + TX < W));
            if (!(rMok && cHok)) hm = 0.0f;
            mrow[posC] = hm;
        }
    };

    auto phaseD = [&](int yo_off, float mag, float gx, float gy,
                      const float* magC, const float* magN) {
        const size_t p = pbase + (size_t)yo_off * W;

        __stcs(gm_out + p, mag);

        /* orientation: comparator fast path; exact fallback near the
           22.5/67.5 bands, on ay==0 with ax<=0, and in the near-pi wedge */
        float ax = gx, ay = gy;
        if (ay < 0.0f) { ax = -ax; ay = -ay; }
        const float pxm = fabsf(ax);
        const float r1 = T1C * pxm;
        const float r2 = T2C * pxm;
        const bool nearb =
            (gx < 0.0f && fabsf(gy) <= WEDGE * (-gx)) ||
            (fabsf(ay - r1) <= BANDEPS * (ay + r1)) ||
            (fabsf(ay - r2) <= BANDEPS * (ay + r2)) ||
            (ay == 0.0f && ax <= 0.0f);
        int k; float orient;
        if (__builtin_expect(nearb, 0)) {
            float go = atan2f(gy, gx) * (180.0f / 3.14159f);
            if (go < 0.0f) go = 360.0f + go;
            go = fmodf(go, 180.0f);
            orient = rintf(go / 45.0f) * 45.0f;
            k = (int)(orient * (1.0f / 45.0f) + 0.5f);
        } else {
            if (ay >= r2)      k = 2;
            else if (ay >= r1) k = (ax > 0.0f) ? 1 : 3;
            else               k = (ax > 0.0f) ? 0 : 4;
            orient = 45.0f * (float)k;
        }
        __stcs(orient_out + p, orient);

        __stcs(early_out + p, (mag < 10.0f) ? 0.0f : mag);

        const int di = (k >= 1 && k <= 3) ? 1 : 0;
        const int dj = (k < 2) ? 1 : ((k == 2) ? 0 : -1);
        const float bias = (k < 4) ? d0b : d1b;

        const float nbv = (di ? magN : magC)[t + 1 + dj];
        const float val = mag - nbv + bias;
        const float th = (val > 0.0f) ? mag : 0.0f;
        __stcs(thin_out + p, th);
        __stcs(thresh_out + p, (th < 10.0f) ? 0.0f : th);
    };

    /* main loop: 2 rows/iteration, 3 barriers/pair */
    int r5 = 0, r3 = 0;    /* i0 % 5, i0 % 3 */
    #pragma unroll 1
    for (int ii = 0; ii < (TY + 8) / 2; ii++) {
        const int i0 = 2 * ii, i1i = i0 + 1;
        const int yA = y0 - 4 + i0;
        const int yB = yA + 1;
        const int r5b = (r5 + 1 == 5) ? 0 : r5 + 1;
        const int r3b = (r3 + 1 == 3) ? 0 : r3 + 1;

        loadA(yA, s_img[0]);
        loadA(yB, s_img[1]);
        __syncthreads();

        phaseB(yA, s_img[0], s_bl[0], r5);
        phaseB(yB, s_img[1], s_bl[1], r5b);
        __syncthreads();

        float nmA, ngxA, ngyA, nmB, ngxB, ngyB;
        phaseC(yA - 3, s_bl[0], s_mag[i0 & 3],  nmA, ngxA, ngyA, r3);
        phaseC(yB - 3, s_bl[1], s_mag[i1i & 3], nmB, ngxB, ngyB, r3b);
        __syncthreads();

        if (ii >= 4) {
            phaseD(i0 - 8,  pm,  pgx,  pgy,  s_mag[(i0 - 1) & 3], s_mag[i0 & 3]);
            phaseD(i1i - 8, nmA, ngxA, ngyA, s_mag[i0 & 3],       s_mag[i1i & 3]);
        }
        pm = nmB; pgx = ngxB; pgy = ngyB;

        r5 += 2; if (r5 >= 5) r5 -= 5;
        r3 += 2; if (r3 >= 3) r3 -= 3;
    }
}

__global__ __launch_bounds__(NT) void canny_kernel(
    const float* __restrict__ img,
    const float* __restrict__ bh_p,  const float* __restrict__ bv_p,
    const float* __restrict__ shb_p, const float* __restrict__ svb_p,
    const float* __restrict__ d0b_p, const float* __restrict__ d1b_p,
    float* __restrict__ out)
{
    __shared__ float s_img[2][CH][LW];
    __shared__ float s_bl[2][CH][BW];
    __shared__ float s_mag[4][BW];
    __shared__ float sh_hB[4][CH][5];
    __shared__ float sh_hs[2][CH][3];
    __shared__ float sh_hd[2][CH][3];

    const int b  = blockIdx.z;
    const int x0 = blockIdx.x * TX;
    const int y0 = blockIdx.y * TY;
    const int t  = threadIdx.x;

    const float bh  = __ldg(bh_p),  bv  = __ldg(bv_p);
    const float shb = __ldg(shb_p), svb = __ldg(svb_p);
    const float d0b = __ldg(d0b_p), d1b = __ldg(d1b_p);

    const float* imgb = img + (size_t)b * CH * NPLANE;
    float* blb = out + (size_t)b * CH * NPLANE;

    const bool interior = (x0 >= 4) && (x0 + TX + 4 <= W) &&
                          (y0 >= 4) && (y0 + TY + 4 <= H);

    if (interior)
        canny_body<true >(imgb, blb, out, b, x0, y0, t,
                          bh, bv, shb, svb, d0b, d1b,
                          s_img, s_bl, s_mag, sh_hB, sh_hs, sh_hd);
    else
        canny_body<false>(imgb, blb, out, b, x0, y0, t,
                          bh, bv, shb, svb, d0b, d1b,
                          s_img, s_bl, s_mag, sh_hB, sh_hs, sh_hd);
}

/* ================================================================== */
extern "C" void kernel_launch(void* const* d_in, const int* in_sizes, int n_in,
                              void* d_out, int out_size)
{
    const float* img = (const float*)d_in[0];
    const float* bh  = (const float*)d_in[1];
    const float* bv  = (const float*)d_in[2];
    const float* shb = (const float*)d_in[3];
    const float* svb = (const float*)d_in[4];
    const float* d0b = (const float*)d_in[5];
    const float* d1b = (const float*)d_in[6];

    dim3 grid(W / TX, H / TY, BATCH);
    canny_kernel<<<grid, NT>>>(img, bh, bv, shb, svb, d0b, d1b, (float*)d_out);

    (void)in_sizes; (void)n_in; (void)out_size;
}